// round 17
// baseline (speedup 1.0000x reference)
#include <cuda_runtime.h>
#include <cuda_bf16.h>
#include <math.h>
#include <stdint.h>

// Problem constants
#define T_ 2048
#define B_ 2
#define E_ 768
#define H_ 12
#define D_ 64
#define F_ 3072
#define M_ (T_ * B_)   // 4096 rows
#define EH (E_ / 2)
#define FH (F_ / 2)

// ---------------------------------------------------------------------------
// Scratch (device globals — no cudaMalloc allowed)
// ---------------------------------------------------------------------------
__device__ uint32_t g_sth[M_ * EH], g_stl[M_ * EH];   // packed state
__device__ uint32_t g_qh[M_ * EH],  g_ql[M_ * EH];    // packed Q (pre-scaled 1/8)
__device__ uint32_t g_kh[M_ * EH],  g_kl[M_ * EH];    // packed K
__device__ float    g_v[M_ * E_];                     // V fp32
__device__ uint32_t g_ch[M_ * EH],  g_cl[M_ * EH];    // packed ctx
__device__ float    g_t0[M_ * E_];                    // attn_out / ffn_out fp32
__device__ float    g_x1[M_ * E_];                    // LN1 out fp32 (residual)
__device__ uint32_t g_x1h[M_ * EH], g_x1l[M_ * EH];   // LN1 out packed
__device__ uint32_t g_h1h[M_ * FH], g_h1l[M_ * FH];   // FFN hidden packed
// pre-split transposed weights: [N][K/2]
__device__ uint32_t g_wqTh[E_ * EH], g_wqTl[E_ * EH];
__device__ uint32_t g_wkTh[E_ * EH], g_wkTl[E_ * EH];
__device__ uint32_t g_wvTh[E_ * EH], g_wvTl[E_ * EH];
__device__ uint32_t g_woTh[E_ * EH], g_woTl[E_ * EH];
__device__ uint32_t g_w1Th[F_ * EH], g_w1Tl[F_ * EH];
__device__ uint32_t g_w2Th[E_ * FH], g_w2Tl[E_ * FH];

// ---------------------------------------------------------------------------
// Helpers (baseline PTX only — compute_103 virtual arch)
// ---------------------------------------------------------------------------
__device__ __forceinline__ uint32_t smem_u32(const void* p) {
    uint32_t a;
    asm("{ .reg .u64 t; cvta.to.shared.u64 t, %1; cvt.u32.u64 %0, t; }" : "=r"(a) : "l"(p));
    return a;
}
__device__ __forceinline__ void cp16(uint32_t dst, const void* src) {
    asm volatile("cp.async.cg.shared.global [%0], [%1], 16;" :: "r"(dst), "l"(src));
}
#define CP_COMMIT() asm volatile("cp.async.commit_group;" ::: "memory")
#define CP_WAIT(n)  asm volatile("cp.async.wait_group %0;" :: "n"(n) : "memory")

__device__ __forceinline__ void bsplit(float x, float y, uint32_t& hi, uint32_t& lo) {
    __nv_bfloat162 h = __floats2bfloat162_rn(x, y);
    const float hx = __low2float(h), hy = __high2float(h);
    __nv_bfloat162 l = __floats2bfloat162_rn(x - hx, y - hy);
    hi = *reinterpret_cast<uint32_t*>(&h);
    lo = *reinterpret_cast<uint32_t*>(&l);
}

__device__ __forceinline__ void mma_bf16(float* d, const uint32_t* a, const uint32_t* b) {
    asm volatile("mma.sync.aligned.m16n8k16.row.col.f32.bf16.bf16.f32 "
                 "{%0,%1,%2,%3}, {%4,%5,%6,%7}, {%8,%9}, {%0,%1,%2,%3};"
                 : "+f"(d[0]), "+f"(d[1]), "+f"(d[2]), "+f"(d[3])
                 : "r"(a[0]), "r"(a[1]), "r"(a[2]), "r"(a[3]), "r"(b[0]), "r"(b[1]));
}

__device__ __forceinline__ void ldm4(uint32_t& r0, uint32_t& r1, uint32_t& r2,
                                     uint32_t& r3, uint32_t a) {
    asm volatile("ldmatrix.sync.aligned.m8n8.x4.shared.b16 {%0,%1,%2,%3}, [%4];"
                 : "=r"(r0), "=r"(r1), "=r"(r2), "=r"(r3) : "r"(a));
}

// ---------------------------------------------------------------------------
// Fused pack kernel: pack_rows (region 0) + 6x transpose-pack (regions 1..6).
// Single launch to avoid per-launch latency of 7 tiny kernels.
// ---------------------------------------------------------------------------
#define PK_ROWS_BLKS (M_ * EH / 256)      // 6144
#define PK_E_BLKS 576                      // 24x24 per ExE weight
#define PK_F_BLKS 2304                     // 96x24 / 24x96

__global__ void __launch_bounds__(256)
pack_all_kernel(const float* __restrict__ state,
                const float* __restrict__ Wq, const float* __restrict__ Wk,
                const float* __restrict__ Wv, const float* __restrict__ Wo,
                const float* __restrict__ W1, const float* __restrict__ W2,
                uint32_t* __restrict__ sth, uint32_t* __restrict__ stl,
                uint32_t* __restrict__ wqh, uint32_t* __restrict__ wql,
                uint32_t* __restrict__ wkh, uint32_t* __restrict__ wkl,
                uint32_t* __restrict__ wvh, uint32_t* __restrict__ wvl,
                uint32_t* __restrict__ woh, uint32_t* __restrict__ wol,
                uint32_t* __restrict__ w1h, uint32_t* __restrict__ w1l,
                uint32_t* __restrict__ w2h, uint32_t* __restrict__ w2l)
{
    __shared__ float t[32][33];
    const int tid = threadIdx.x;
    int bid = blockIdx.x;

    if (bid < PK_ROWS_BLKS) {
        const int i = bid * 256 + tid;
        const float2 v = *(const float2*)&state[2 * i];
        uint32_t hi, lo;
        bsplit(v.x, v.y, hi, lo);
        sth[i] = hi;
        stl[i] = lo;
        return;
    }
    bid -= PK_ROWS_BLKS;

    const float* in;
    uint32_t *oh, *ol;
    int R, gx, C, idx;
    if (bid < PK_E_BLKS)          { in = Wq; oh = wqh; ol = wql; R = E_; C = E_; gx = 24; idx = bid; }
    else if (bid < 2 * PK_E_BLKS) { in = Wk; oh = wkh; ol = wkl; R = E_; C = E_; gx = 24; idx = bid - PK_E_BLKS; }
    else if (bid < 3 * PK_E_BLKS) { in = Wv; oh = wvh; ol = wvl; R = E_; C = E_; gx = 24; idx = bid - 2 * PK_E_BLKS; }
    else if (bid < 4 * PK_E_BLKS) { in = Wo; oh = woh; ol = wol; R = E_; C = E_; gx = 24; idx = bid - 3 * PK_E_BLKS; }
    else if (bid < 4 * PK_E_BLKS + PK_F_BLKS)
                                  { in = W1; oh = w1h; ol = w1l; R = E_; C = F_; gx = 96; idx = bid - 4 * PK_E_BLKS; }
    else                          { in = W2; oh = w2h; ol = w2l; R = F_; C = E_; gx = 24; idx = bid - 4 * PK_E_BLKS - PK_F_BLKS; }

    const int bx = (idx % gx) * 32;   // n offset
    const int by = (idx / gx) * 32;   // k offset
    const int x = tid & 31, y = tid >> 5;
#pragma unroll
    for (int j = 0; j < 32; j += 8)
        t[y + j][x] = in[(size_t)(by + y + j) * C + bx + x];
    __syncthreads();
    const int KH2 = R >> 1;
#pragma unroll
    for (int i = 0; i < 2; i++) {
        const int n = (tid >> 4) + i * 16;
        const int kp = tid & 15;
        uint32_t hi, lo;
        bsplit(t[2 * kp][n], t[2 * kp + 1][n], hi, lo);
        oh[(size_t)(bx + n) * KH2 + (by >> 1) + kp] = hi;
        ol[(size_t)(bx + n) * KH2 + (by >> 1) + kp] = lo;
    }
}

// ---------------------------------------------------------------------------
// Shared GEMM mainloop core, ONE barrier per K-iter.
// ---------------------------------------------------------------------------
#define GP_STR 20
#define GP_TILE (128 * GP_STR)          // 2560 u32
#define GP_STAGE (4 * GP_TILE)          // Ah,Al,Bh,Bl
#define GEMM_SMEM (2 * GP_STAGE * 4)    // 81920 bytes

__device__ __forceinline__ void gemm_core(
    const uint32_t* __restrict__ Ah, const uint32_t* __restrict__ Al,
    const uint32_t* __restrict__ Bh, const uint32_t* __restrict__ Bl,
    int KH, int by, int bx, uint32_t sb, int tid, float acc[4][4][4])
{
    const int wid = tid >> 5, lane = tid & 31;
    const int warp_m = (wid >> 2) * 64;
    const int warp_n = (wid & 3) * 32;

    const int arow_l = warp_m + (lane & 15);
    const int acol_l = (lane >> 4) << 2;
    const int brow_l = warp_n + (lane & 7) + ((lane >> 4) << 3);
    const int bcol_l = ((lane >> 3) & 1) << 2;

    const int NT = KH / 16;

    auto load_stage = [&](int buf, int kt) {
        const uint32_t base = sb + (uint32_t)(buf * GP_STAGE) * 4u;
#pragma unroll
        for (int i = 0; i < 2; i++) {
            const int id = tid + i * 256;
            const int row = id >> 2, c4 = id & 3;
            const uint32_t so = (uint32_t)(row * GP_STR + c4 * 4) * 4u;
            const size_t ga = (size_t)(by + row) * KH + kt * 16 + c4 * 4;
            const size_t gb = (size_t)(bx + row) * KH + kt * 16 + c4 * 4;
            cp16(base + so, &Ah[ga]);
            cp16(base + (uint32_t)(GP_TILE * 4) + so, &Al[ga]);
            cp16(base + (uint32_t)(2 * GP_TILE * 4) + so, &Bh[gb]);
            cp16(base + (uint32_t)(3 * GP_TILE * 4) + so, &Bl[gb]);
        }
        CP_COMMIT();
    };

    load_stage(0, 0);

    for (int kt = 0; kt < NT; kt++) {
        CP_WAIT(0);
        __syncthreads();   // buf[kt&1] visible; all threads done computing buf[kt&1] last round
        if (kt + 1 < NT) load_stage((kt + 1) & 1, kt + 1);   // fills other buffer, overlaps compute

        const uint32_t stg = sb + (uint32_t)((kt & 1) * GP_STAGE) * 4u;

#pragma unroll
        for (int j = 0; j < 2; j++) {
            uint32_t ah[4][4], al[4][4];
#pragma unroll
            for (int mt = 0; mt < 4; mt++) {
                const uint32_t aa = stg +
                    (uint32_t)((arow_l + mt * 16) * GP_STR + j * 8 + acol_l) * 4u;
                ldm4(ah[mt][0], ah[mt][1], ah[mt][2], ah[mt][3], aa);
                ldm4(al[mt][0], al[mt][1], al[mt][2], al[mt][3], aa + GP_TILE * 4);
            }
            uint32_t bh2[4][2], bl2[4][2];
#pragma unroll
            for (int p = 0; p < 2; p++) {
                const uint32_t ba = stg + (uint32_t)(2 * GP_TILE) * 4u +
                    (uint32_t)((brow_l + p * 16) * GP_STR + j * 8 + bcol_l) * 4u;
                ldm4(bh2[2 * p][0], bh2[2 * p][1], bh2[2 * p + 1][0], bh2[2 * p + 1][1], ba);
                ldm4(bl2[2 * p][0], bl2[2 * p][1], bl2[2 * p + 1][0], bl2[2 * p + 1][1],
                     ba + GP_TILE * 4);
            }
#pragma unroll
            for (int nt = 0; nt < 4; nt++)
#pragma unroll
                for (int mt = 0; mt < 4; mt++) {
                    mma_bf16(acc[mt][nt], ah[mt], bh2[nt]);
                    mma_bf16(acc[mt][nt], ah[mt], bl2[nt]);
                    mma_bf16(acc[mt][nt], al[mt], bh2[nt]);
                }
        }
    }
}

// generic GEMM: fp32 or packed output
__global__ void __launch_bounds__(256, 2)
gemm_pk_kernel(const uint32_t* __restrict__ Ah, const uint32_t* __restrict__ Al,
               const uint32_t* __restrict__ Bh, const uint32_t* __restrict__ Bl,
               const float* __restrict__ bias,
               float* __restrict__ outF, uint32_t* __restrict__ outH,
               uint32_t* __restrict__ outL,
               int KH, int Ndim, int packout, int relu, float scale)
{
    extern __shared__ uint32_t smu[];
    const uint32_t sb = smem_u32(smu);
    const int tid = threadIdx.x;
    const int wid = tid >> 5, lane = tid & 31;
    const int by = blockIdx.y * 128, bx = blockIdx.x * 128;
    const int warp_m = (wid >> 2) * 64, warp_n = (wid & 3) * 32;
    const int g = lane >> 2, c = lane & 3;

    float acc[4][4][4];
#pragma unroll
    for (int mt = 0; mt < 4; mt++)
#pragma unroll
        for (int nt = 0; nt < 4; nt++)
#pragma unroll
            for (int i = 0; i < 4; i++) acc[mt][nt][i] = 0.f;

    gemm_core(Ah, Al, Bh, Bl, KH, by, bx, sb, tid, acc);

    const int NH = Ndim >> 1;
#pragma unroll
    for (int mt = 0; mt < 4; mt++) {
        const int r0 = by + warp_m + mt * 16 + g;
#pragma unroll
        for (int nt = 0; nt < 4; nt++) {
            const int c0 = bx + warp_n + nt * 8 + 2 * c;
            const float b0 = bias[c0], b1 = bias[c0 + 1];
            float v00 = (acc[mt][nt][0] + b0) * scale;
            float v01 = (acc[mt][nt][1] + b1) * scale;
            float v10 = (acc[mt][nt][2] + b0) * scale;
            float v11 = (acc[mt][nt][3] + b1) * scale;
            if (relu) {
                v00 = fmaxf(v00, 0.f); v01 = fmaxf(v01, 0.f);
                v10 = fmaxf(v10, 0.f); v11 = fmaxf(v11, 0.f);
            }
            if (packout) {
                uint32_t hi, lo;
                bsplit(v00, v01, hi, lo);
                outH[(size_t)r0 * NH + (c0 >> 1)] = hi;
                outL[(size_t)r0 * NH + (c0 >> 1)] = lo;
                bsplit(v10, v11, hi, lo);
                outH[(size_t)(r0 + 8) * NH + (c0 >> 1)] = hi;
                outL[(size_t)(r0 + 8) * NH + (c0 >> 1)] = lo;
            } else {
                float2 w0, w1;
                w0.x = v00; w0.y = v01; w1.x = v10; w1.y = v11;
                *(float2*)&outF[(size_t)r0 * Ndim + c0] = w0;
                *(float2*)&outF[(size_t)(r0 + 8) * Ndim + c0] = w1;
            }
        }
    }
}

// fused QKV GEMM: blockIdx.x region-dispatch (0..5 Q, 6..11 K, 12..17 V)
__global__ void __launch_bounds__(256, 2)
gemm_qkv_kernel(const uint32_t* __restrict__ Ah, const uint32_t* __restrict__ Al,
                const uint32_t* __restrict__ wqh, const uint32_t* __restrict__ wql,
                const uint32_t* __restrict__ wkh, const uint32_t* __restrict__ wkl,
                const uint32_t* __restrict__ wvh, const uint32_t* __restrict__ wvl,
                const float* __restrict__ bq, const float* __restrict__ bk,
                const float* __restrict__ bv,
                uint32_t* __restrict__ qh, uint32_t* __restrict__ ql,
                uint32_t* __restrict__ kh, uint32_t* __restrict__ kl,
                float* __restrict__ vout)
{
    extern __shared__ uint32_t smu[];
    const uint32_t sb = smem_u32(smu);
    const int region = blockIdx.x / 6;
    const int bx = (blockIdx.x % 6) * 128;
    const int by = blockIdx.y * 128;
    const uint32_t* Bh = (region == 0) ? wqh : (region == 1) ? wkh : wvh;
    const uint32_t* Bl = (region == 0) ? wql : (region == 1) ? wkl : wvl;
    const float* bias = (region == 0) ? bq : (region == 1) ? bk : bv;
    const float scale = (region == 0) ? 0.125f : 1.f;

    const int tid = threadIdx.x;
    const int wid = tid >> 5, lane = tid & 31;
    const int warp_m = (wid >> 2) * 64, warp_n = (wid & 3) * 32;
    const int g = lane >> 2, c = lane & 3;

    float acc[4][4][4];
#pragma unroll
    for (int mt = 0; mt < 4; mt++)
#pragma unroll
        for (int nt = 0; nt < 4; nt++)
#pragma unroll
            for (int i = 0; i < 4; i++) acc[mt][nt][i] = 0.f;

    gemm_core(Ah, Al, Bh, Bl, EH, by, bx, sb, tid, acc);

    uint32_t* outH = (region == 0) ? qh : kh;
    uint32_t* outL = (region == 0) ? ql : kl;
#pragma unroll
    for (int mt = 0; mt < 4; mt++) {
        const int r0 = by + warp_m + mt * 16 + g;
#pragma unroll
        for (int nt = 0; nt < 4; nt++) {
            const int c0 = bx + warp_n + nt * 8 + 2 * c;
            const float b0 = bias[c0], b1 = bias[c0 + 1];
            const float v00 = (acc[mt][nt][0] + b0) * scale;
            const float v01 = (acc[mt][nt][1] + b1) * scale;
            const float v10 = (acc[mt][nt][2] + b0) * scale;
            const float v11 = (acc[mt][nt][3] + b1) * scale;
            if (region < 2) {
                uint32_t hi, lo;
                bsplit(v00, v01, hi, lo);
                outH[(size_t)r0 * EH + (c0 >> 1)] = hi;
                outL[(size_t)r0 * EH + (c0 >> 1)] = lo;
                bsplit(v10, v11, hi, lo);
                outH[(size_t)(r0 + 8) * EH + (c0 >> 1)] = hi;
                outL[(size_t)(r0 + 8) * EH + (c0 >> 1)] = lo;
            } else {
                float2 w0, w1;
                w0.x = v00; w0.y = v01; w1.x = v10; w1.y = v11;
                *(float2*)&vout[(size_t)r0 * E_ + c0] = w0;
                *(float2*)&vout[(size_t)(r0 + 8) * E_ + c0] = w1;
            }
        }
    }
}

// ---------------------------------------------------------------------------
// Tensor-core flash attention. Mask precomputed once (bytes + per-tile skip
// flags in smem); 2 barriers per live key tile, 1 per skipped tile.
// ---------------------------------------------------------------------------
#define FP_STR 36
#define FQH 0
#define FQL (FQH + 128 * FP_STR)
#define FKH (FQL + 128 * FP_STR)
#define FKL (FKH + 64 * FP_STR)
#define FVH (FKL + 64 * FP_STR)
#define FVL (FVH + 64 * FP_STR)
#define FMKB (FVL + 64 * FP_STR)          // 2048 mask bytes = 512 words
#define FSKIP (FMKB + 512)                // 32 skip flags
#define FA_SMEM ((FSKIP + 32) * 4)

__global__ void __launch_bounds__(256, 2)
flash_attn_pk_kernel(const uint32_t* __restrict__ Qh, const uint32_t* __restrict__ Ql,
                     const uint32_t* __restrict__ Kh, const uint32_t* __restrict__ Kl,
                     const float* __restrict__ V, const int* __restrict__ mask,
                     uint32_t* __restrict__ ctxh, uint32_t* __restrict__ ctxl)
{
    extern __shared__ uint32_t us[];
    const uint32_t sbF = smem_u32(us);
    char* mkb = (char*)(us + FMKB);
    int* skip = (int*)(us + FSKIP);

    const int t0 = blockIdx.x * 128;
    const int b = blockIdx.y / H_;
    const int h = blockIdx.y % H_;
    const int tid = threadIdx.x;
    const int w = tid >> 5, lane = tid & 31;
    const int g = lane >> 2, c = lane & 3;
    const int wm = w * 16;

    const int qrow_l = wm + (lane & 15);
    const int qcol_l = (lane >> 4) << 2;
    const int krow_l = (lane & 7) + ((lane >> 4) << 3);
    const int kcol_l = ((lane >> 3) & 1) << 2;

    // ---- one-time: Q tile + mask bytes + per-tile skip flags ----
#pragma unroll
    for (int i = 0; i < 4; i++) {
        const int id = tid + i * 256;
        const int r = id >> 3, c4 = (id & 7) * 4;
        const size_t go = ((size_t)(t0 + r) * B_ + b) * EH + h * 32 + c4;
        *(uint4*)&us[FQH + r * FP_STR + c4] = *(const uint4*)&Qh[go];
        *(uint4*)&us[FQL + r * FP_STR + c4] = *(const uint4*)&Ql[go];
    }
#pragma unroll
    for (int i = 0; i < 8; i++)
        mkb[tid + i * 256] = (char)(mask[(size_t)b * T_ + tid + i * 256] != 0);
    __syncthreads();
    if (tid < 32) {
        int all = 1;
#pragma unroll
        for (int j = 0; j < 64; j++) all &= (int)mkb[tid * 64 + j];
        skip[tid] = all;
    }
    __syncthreads();

    float o[8][4];
#pragma unroll
    for (int nt = 0; nt < 8; nt++)
#pragma unroll
        for (int i = 0; i < 4; i++) o[nt][i] = 0.f;
    float m0 = -INFINITY, m1 = -INFINITY, l0s = 0.f, l1s = 0.f;

    for (int s0 = 0; s0 < T_; s0 += 64) {
        __syncthreads();   // K/V buffer reuse barrier
        if (skip[s0 >> 6]) continue;   // uniform smem read, whole block skips

        // packed K tile [64 x 32 kp] hi+lo
#pragma unroll
        for (int i = 0; i < 2; i++) {
            const int id = tid + i * 256;
            const int r = id >> 3, c4 = (id & 7) * 4;
            const size_t go = ((size_t)(s0 + r) * B_ + b) * EH + h * 32 + c4;
            *(uint4*)&us[FKH + r * FP_STR + c4] = *(const uint4*)&Kh[go];
            *(uint4*)&us[FKL + r * FP_STR + c4] = *(const uint4*)&Kl[go];
        }
        // V tile transposed + split: Vt[d][key-pair]
#pragma unroll
        for (int i = 0; i < 2; i++) {
            const int id = tid + i * 256;
            const int kp = id & 31, dblk = id >> 5;
            const float4 va = *(const float4*)&V[((size_t)(s0 + 2 * kp) * B_ + b) * E_ + h * 64 + dblk * 4];
            const float4 vb = *(const float4*)&V[((size_t)(s0 + 2 * kp + 1) * B_ + b) * E_ + h * 64 + dblk * 4];
            uint32_t hi, lo;
            bsplit(va.x, vb.x, hi, lo);
            us[FVH + (dblk * 4 + 0) * FP_STR + kp] = hi; us[FVL + (dblk * 4 + 0) * FP_STR + kp] = lo;
            bsplit(va.y, vb.y, hi, lo);
            us[FVH + (dblk * 4 + 1) * FP_STR + kp] = hi; us[FVL + (dblk * 4 + 1) * FP_STR + kp] = lo;
            bsplit(va.z, vb.z, hi, lo);
            us[FVH + (dblk * 4 + 2) * FP_STR + kp] = hi; us[FVL + (dblk * 4 + 2) * FP_STR + kp] = lo;
            bsplit(va.w, vb.w, hi, lo);
            us[FVH + (dblk * 4 + 3) * FP_STR + kp] = hi; us[FVL + (dblk * 4 + 3) * FP_STR + kp] = lo;
        }
        __syncthreads();

        // ---- S = (Q/8) K^T ----
        float sa[8][4];
#pragma unroll
        for (int nt = 0; nt < 8; nt++)
#pragma unroll
            for (int i = 0; i < 4; i++) sa[nt][i] = 0.f;

#pragma unroll
        for (int j = 0; j < 4; j++) {
            uint32_t qh[4], ql[4];
            const uint32_t qa = sbF + (uint32_t)(FQH + qrow_l * FP_STR + j * 8 + qcol_l) * 4u;
            ldm4(qh[0], qh[1], qh[2], qh[3], qa);
            ldm4(ql[0], ql[1], ql[2], ql[3], qa + (FQL - FQH) * 4);
#pragma unroll
            for (int p = 0; p < 4; p++) {
                uint32_t bh2[2][2], bl2[2][2];
                const uint32_t ka = sbF +
                    (uint32_t)(FKH + (krow_l + p * 16) * FP_STR + j * 8 + kcol_l) * 4u;
                ldm4(bh2[0][0], bh2[0][1], bh2[1][0], bh2[1][1], ka);
                ldm4(bl2[0][0], bl2[0][1], bl2[1][0], bl2[1][1], ka + (FKL - FKH) * 4);
                mma_bf16(sa[2 * p], qh, bh2[0]);
                mma_bf16(sa[2 * p], qh, bl2[0]);
                mma_bf16(sa[2 * p], ql, bh2[0]);
                mma_bf16(sa[2 * p + 1], qh, bh2[1]);
                mma_bf16(sa[2 * p + 1], qh, bl2[1]);
                mma_bf16(sa[2 * p + 1], ql, bh2[1]);
            }
        }

        // ---- online softmax (mask from precomputed bytes) ----
        float mx0 = -INFINITY, mx1 = -INFINITY;
#pragma unroll
        for (int nt = 0; nt < 8; nt++) {
            const int col0 = s0 + nt * 8 + 2 * c, col1 = col0 + 1;
            const bool k0m = mkb[col0] != 0, k1m = mkb[col1] != 0;
            float s0v = sa[nt][0]; if (k0m) s0v = -INFINITY;
            float s1v = sa[nt][1]; if (k1m) s1v = -INFINITY;
            float s2v = sa[nt][2]; if (k0m) s2v = -INFINITY;
            float s3v = sa[nt][3]; if (k1m) s3v = -INFINITY;
            sa[nt][0] = s0v; sa[nt][1] = s1v; sa[nt][2] = s2v; sa[nt][3] = s3v;
            mx0 = fmaxf(mx0, fmaxf(s0v, s1v));
            mx1 = fmaxf(mx1, fmaxf(s2v, s3v));
        }
        mx0 = fmaxf(mx0, __shfl_xor_sync(0xffffffffu, mx0, 1));
        mx0 = fmaxf(mx0, __shfl_xor_sync(0xffffffffu, mx0, 2));
        mx1 = fmaxf(mx1, __shfl_xor_sync(0xffffffffu, mx1, 1));
        mx1 = fmaxf(mx1, __shfl_xor_sync(0xffffffffu, mx1, 2));

        const float mn0 = fmaxf(m0, mx0), mn1 = fmaxf(m1, mx1);
        const float al0 = __expf(m0 - mn0), al1 = __expf(m1 - mn1);
        m0 = mn0; m1 = mn1;

        uint32_t phl[8], phh[8], pll[8], plh[8];
        float su0 = 0.f, su1 = 0.f;
#pragma unroll
        for (int nt = 0; nt < 8; nt++) {
            const float p0 = __expf(sa[nt][0] - mn0);
            const float p1 = __expf(sa[nt][1] - mn0);
            const float p2 = __expf(sa[nt][2] - mn1);
            const float p3 = __expf(sa[nt][3] - mn1);
            su0 += p0 + p1; su1 += p2 + p3;
            bsplit(p0, p1, phl[nt], pll[nt]);
            bsplit(p2, p3, phh[nt], plh[nt]);
        }
        su0 += __shfl_xor_sync(0xffffffffu, su0, 1);
        su0 += __shfl_xor_sync(0xffffffffu, su0, 2);
        su1 += __shfl_xor_sync(0xffffffffu, su1, 1);
        su1 += __shfl_xor_sync(0xffffffffu, su1, 2);
        l0s = l0s * al0 + su0;
        l1s = l1s * al1 + su1;
#pragma unroll
        for (int nt = 0; nt < 8; nt++) {
            o[nt][0] *= al0; o[nt][1] *= al0;
            o[nt][2] *= al1; o[nt][3] *= al1;
        }

        // ---- O += P V ----
#pragma unroll
        for (int j = 0; j < 4; j++) {
            uint32_t ah[4], al2[4];
            ah[0] = phl[2 * j];     ah[1] = phh[2 * j];
            ah[2] = phl[2 * j + 1]; ah[3] = phh[2 * j + 1];
            al2[0] = pll[2 * j];     al2[1] = plh[2 * j];
            al2[2] = pll[2 * j + 1]; al2[3] = plh[2 * j + 1];
#pragma unroll
            for (int p = 0; p < 4; p++) {
                uint32_t bh2[2][2], bl2[2][2];
                const uint32_t va = sbF +
                    (uint32_t)(FVH + (krow_l + p * 16) * FP_STR + j * 8 + kcol_l) * 4u;
                ldm4(bh2[0][0], bh2[0][1], bh2[1][0], bh2[1][1], va);
                ldm4(bl2[0][0], bl2[0][1], bl2[1][0], bl2[1][1], va + (FVL - FVH) * 4);
                mma_bf16(o[2 * p], ah, bh2[0]);
                mma_bf16(o[2 * p], ah, bl2[0]);
                mma_bf16(o[2 * p], al2, bh2[0]);
                mma_bf16(o[2 * p + 1], ah, bh2[1]);
                mma_bf16(o[2 * p + 1], ah, bl2[1]);
                mma_bf16(o[2 * p + 1], al2, bh2[1]);
            }
        }
    }

    // writeout: packed ctx
    const float i0 = 1.f / l0s, i1 = 1.f / l1s;
#pragma unroll
    for (int nt = 0; nt < 8; nt++) {
        const int kp = h * 32 + nt * 4 + c;
        uint32_t hi, lo;
        bsplit(o[nt][0] * i0, o[nt][1] * i0, hi, lo);
        ctxh[((size_t)(t0 + wm + g) * B_ + b) * EH + kp] = hi;
        ctxl[((size_t)(t0 + wm + g) * B_ + b) * EH + kp] = lo;
        bsplit(o[nt][2] * i1, o[nt][3] * i1, hi, lo);
        ctxh[((size_t)(t0 + wm + g + 8) * B_ + b) * EH + kp] = hi;
        ctxl[((size_t)(t0 + wm + g + 8) * B_ + b) * EH + kp] = lo;
    }
}

// ---------------------------------------------------------------------------
// Fused add-residual + LayerNorm
// ---------------------------------------------------------------------------
__device__ __forceinline__ float warpReduceSum(float v) {
#pragma unroll
    for (int o = 16; o; o >>= 1) v += __shfl_xor_sync(0xffffffffu, v, o);
    return v;
}

__global__ void __launch_bounds__(256)
add_ln_kernel(const float* __restrict__ a, const float* __restrict__ r,
              const float* __restrict__ g, const float* __restrict__ be,
              float* __restrict__ out)
{
    const int row = blockIdx.x;
    const int tid = threadIdx.x;
    const float* pa = a + (size_t)row * E_;
    const float* pr = r + (size_t)row * E_;

    float v0 = pa[tid] + pr[tid];
    float v1 = pa[tid + 256] + pr[tid + 256];
    float v2 = pa[tid + 512] + pr[tid + 512];

    __shared__ float red[8];
    const int wid = tid >> 5, lane = tid & 31;

    float s = warpReduceSum(v0 + v1 + v2);
    if (lane == 0) red[wid] = s;
    __syncthreads();
    float tot = 0.f;
#pragma unroll
    for (int i = 0; i < 8; i++) tot += red[i];
    const float mean = tot * (1.f / (float)E_);

    float d0 = v0 - mean, d1 = v1 - mean, d2 = v2 - mean;
    float sq = warpReduceSum(d0 * d0 + d1 * d1 + d2 * d2);
    __syncthreads();
    if (lane == 0) red[wid] = sq;
    __syncthreads();
    tot = 0.f;
#pragma unroll
    for (int i = 0; i < 8; i++) tot += red[i];
    const float inv = rsqrtf(tot * (1.f / (float)E_) + 1e-5f);

    float* po = out + (size_t)row * E_;
    po[tid]       = d0 * inv * g[tid]       + be[tid];
    po[tid + 256] = d1 * inv * g[tid + 256] + be[tid + 256];
    po[tid + 512] = d2 * inv * g[tid + 512] + be[tid + 512];
}

__global__ void __launch_bounds__(128)
add_ln_pack_kernel(const float* __restrict__ a, const float* __restrict__ r,
                   const float* __restrict__ g, const float* __restrict__ be,
                   float* __restrict__ outF, uint32_t* __restrict__ outH,
                   uint32_t* __restrict__ outL)
{
    const int row = blockIdx.x;
    const int tid = threadIdx.x;
    const float* pa = a + (size_t)row * E_;
    const float* pr = r + (size_t)row * E_;

    float2 v[3];
#pragma unroll
    for (int i = 0; i < 3; i++) {
        const int o = 2 * (tid + i * 128);
        const float2 x = *(const float2*)&pa[o];
        const float2 y = *(const float2*)&pr[o];
        v[i].x = x.x + y.x;
        v[i].y = x.y + y.y;
    }

    __shared__ float red[4];
    const int wid = tid >> 5, lane = tid & 31;

    float s = warpReduceSum(v[0].x + v[0].y + v[1].x + v[1].y + v[2].x + v[2].y);
    if (lane == 0) red[wid] = s;
    __syncthreads();
    float tot = red[0] + red[1] + red[2] + red[3];
    const float mean = tot * (1.f / (float)E_);

    float sq = 0.f;
#pragma unroll
    for (int i = 0; i < 3; i++) {
        v[i].x -= mean; v[i].y -= mean;
        sq += v[i].x * v[i].x + v[i].y * v[i].y;
    }
    sq = warpReduceSum(sq);
    __syncthreads();
    if (lane == 0) red[wid] = sq;
    __syncthreads();
    tot = red[0] + red[1] + red[2] + red[3];
    const float inv = rsqrtf(tot * (1.f / (float)E_) + 1e-5f);

    float* po = outF + (size_t)row * E_;
    uint32_t* ph = outH + (size_t)row * EH;
    uint32_t* pl = outL + (size_t)row * EH;
#pragma unroll
    for (int i = 0; i < 3; i++) {
        const int p = tid + i * 128;
        const float2 gg = *(const float2*)&g[2 * p];
        const float2 bb = *(const float2*)&be[2 * p];
        float2 w;
        w.x = v[i].x * inv * gg.x + bb.x;
        w.y = v[i].y * inv * gg.y + bb.y;
        *(float2*)&po[2 * p] = w;
        uint32_t hi, lo;
        bsplit(w.x, w.y, hi, lo);
        ph[p] = hi;
        pl[p] = lo;
    }
}

// ---------------------------------------------------------------------------
// Launch
// ---------------------------------------------------------------------------
extern "C" void kernel_launch(void* const* d_in, const int* in_sizes, int n_in,
                              void* d_out, int out_size)
{
    const float* state = (const float*)d_in[0];
    const int* mask = (const int*)d_in[1];
    const float* Wq = (const float*)d_in[2];
    const float* bq = (const float*)d_in[3];
    const float* Wk = (const float*)d_in[4];
    const float* bk = (const float*)d_in[5];
    const float* Wv = (const float*)d_in[6];
    const float* bv = (const float*)d_in[7];
    const float* Wo = (const float*)d_in[8];
    const float* bo = (const float*)d_in[9];
    const float* ln1g = (const float*)d_in[10];
    const float* ln1b = (const float*)d_in[11];
    const float* W1 = (const float*)d_in[12];
    const float* b1 = (const float*)d_in[13];
    const float* W2 = (const float*)d_in[14];
    const float* b2 = (const float*)d_in[15];
    const float* ln2g = (const float*)d_in[16];
    const float* ln2b = (const float*)d_in[17];
    float* out = (float*)d_out;

    uint32_t *sth, *stl, *qh, *ql, *kh, *kl, *ch, *cl, *x1h, *x1l, *h1h, *h1l;
    float *vp, *t0p, *x1p;
    uint32_t *wqh, *wql, *wkh, *wkl, *wvh, *wvl, *woh, *wol, *w1h, *w1l, *w2h, *w2l;
    cudaGetSymbolAddress((void**)&sth, g_sth); cudaGetSymbolAddress((void**)&stl, g_stl);
    cudaGetSymbolAddress((void**)&qh, g_qh);   cudaGetSymbolAddress((void**)&ql, g_ql);
    cudaGetSymbolAddress((void**)&kh, g_kh);   cudaGetSymbolAddress((void**)&kl, g_kl);
    cudaGetSymbolAddress((void**)&vp, g_v);
    cudaGetSymbolAddress((void**)&ch, g_ch);   cudaGetSymbolAddress((void**)&cl, g_cl);
    cudaGetSymbolAddress((void**)&t0p, g_t0);
    cudaGetSymbolAddress((void**)&x1p, g_x1);
    cudaGetSymbolAddress((void**)&x1h, g_x1h); cudaGetSymbolAddress((void**)&x1l, g_x1l);
    cudaGetSymbolAddress((void**)&h1h, g_h1h); cudaGetSymbolAddress((void**)&h1l, g_h1l);
    cudaGetSymbolAddress((void**)&wqh, g_wqTh); cudaGetSymbolAddress((void**)&wql, g_wqTl);
    cudaGetSymbolAddress((void**)&wkh, g_wkTh); cudaGetSymbolAddress((void**)&wkl, g_wkTl);
    cudaGetSymbolAddress((void**)&wvh, g_wvTh); cudaGetSymbolAddress((void**)&wvl, g_wvTl);
    cudaGetSymbolAddress((void**)&woh, g_woTh); cudaGetSymbolAddress((void**)&wol, g_woTl);
    cudaGetSymbolAddress((void**)&w1h, g_w1Th); cudaGetSymbolAddress((void**)&w1l, g_w1Tl);
    cudaGetSymbolAddress((void**)&w2h, g_w2Th); cudaGetSymbolAddress((void**)&w2l, g_w2Tl);

    cudaFuncSetAttribute(gemm_pk_kernel, cudaFuncAttributeMaxDynamicSharedMemorySize, GEMM_SMEM);
    cudaFuncSetAttribute(gemm_qkv_kernel, cudaFuncAttributeMaxDynamicSharedMemorySize, GEMM_SMEM);
    cudaFuncSetAttribute(flash_attn_pk_kernel, cudaFuncAttributeMaxDynamicSharedMemorySize, FA_SMEM);

    // single fused pack launch (state + 6 weights)
    const int pack_blocks = PK_ROWS_BLKS + 4 * PK_E_BLKS + 2 * PK_F_BLKS;   // 13056
    pack_all_kernel<<<pack_blocks, 256>>>(state, Wq, Wk, Wv, Wo, W1, W2,
                                          sth, stl, wqh, wql, wkh, wkl, wvh, wvl,
                                          woh, wol, w1h, w1l, w2h, w2l);

    dim3 gQKV(18, M_ / 128);
    dim3 gE(E_ / 128, M_ / 128);
    dim3 gF(F_ / 128, M_ / 128);

    // fused QKV projection
    gemm_qkv_kernel<<<gQKV, 256, GEMM_SMEM>>>(sth, stl, wqh, wql, wkh, wkl, wvh, wvl,
                                              bq, bk, bv, qh, ql, kh, kl, vp);

    // attention -> packed ctx
    flash_attn_pk_kernel<<<dim3(T_ / 128, B_ * H_), 256, FA_SMEM>>>(qh, ql, kh, kl, vp, mask, ch, cl);

    // output projection + LN1
    gemm_pk_kernel<<<gE, 256, GEMM_SMEM>>>(ch, cl, woh, wol, bo, t0p, nullptr, nullptr, EH, E_, 0, 0, 1.f);
    add_ln_pack_kernel<<<M_, 128>>>(t0p, state, ln1g, ln1b, x1p, x1h, x1l);

    // FFN + LN2
    gemm_pk_kernel<<<gF, 256, GEMM_SMEM>>>(x1h, x1l, w1h, w1l, b1, nullptr, h1h, h1l, EH, F_, 1, 1, 1.f);
    gemm_pk_kernel<<<gE, 256, GEMM_SMEM>>>(h1h, h1l, w2h, w2l, b2, t0p, nullptr, nullptr, FH, E_, 0, 0, 1.f);
    add_ln_kernel<<<M_, 256>>>(t0p, x1p, ln2g, ln2b, out);
}